// round 4
// baseline (speedup 1.0000x reference)
#include <cuda_runtime.h>
#include <cstdint>

// Inv1x1MM_SVD, C=16, 65536 positions. 16 lanes per position, lane j owns
// column j in packed f32x2 registers. MGS; finished column k is read back
// from a shared-memory column cache. Per-step body predicated on (j > k) so
// retired lanes issue no LDS/STS wavefronts. Fresh norms each step for
// stability on ill-conditioned inputs.

constexpr int NPOS = 8 * 8192;
constexpr int PSTRIDE = 528;
constexpr int POS_PER_BLOCK = 16;      // 256 threads
constexpr int BUFF = 336;              // floats per position buffer

#define FMA2(d, a, b, c) asm("fma.rn.f32x2 %0, %1, %2, %3;" : "=l"(d) : "l"(a), "l"(b), "l"(c))
#define MUL2(d, a, b)    asm("mul.rn.f32x2 %0, %1, %2;"     : "=l"(d) : "l"(a), "l"(b))
#define PACK2(d, lo, hi) asm("mov.b64 %0, {%1, %2};"        : "=l"(d) : "f"(lo), "f"(hi))
#define UNPACK2(lo, hi, d) asm("mov.b64 {%0, %1}, %2;" : "=f"(lo), "=f"(hi) : "l"(d))

__device__ __forceinline__ uint32_t smem_u32(const void* p) {
    uint32_t a;
    asm("{ .reg .u64 t; cvta.to.shared.u64 t, %1; cvt.u32.u64 %0, t; }" : "=r"(a) : "l"(p));
    return a;
}
__device__ __forceinline__ void lds2(uint64_t& a, uint64_t& b, uint32_t addr) {
    asm volatile("ld.shared.v2.u64 {%0, %1}, [%2];" : "=l"(a), "=l"(b) : "r"(addr));
}
__device__ __forceinline__ void sts2(uint32_t addr, uint64_t a, uint64_t b) {
    asm volatile("st.shared.v2.u64 [%0], {%1, %2};" :: "r"(addr), "l"(a), "l"(b) : "memory");
}
__device__ __forceinline__ float ldsf(uint32_t addr) {
    float v;
    asm volatile("ld.shared.f32 %0, [%1];" : "=f"(v) : "r"(addr));
    return v;
}
__device__ __forceinline__ void stsf(uint32_t addr, float v) {
    asm volatile("st.shared.f32 [%0], %1;" :: "r"(addr), "f"(v) : "memory");
}

// dot of two packed 16-vectors -> scalar, two accumulator trees
__device__ __forceinline__ float dot16(const uint64_t (&a)[8], const uint64_t (&b)[8]) {
    uint64_t s0, s1;
    MUL2(s0, a[0], b[0]);
    MUL2(s1, a[1], b[1]);
    FMA2(s0, a[2], b[2], s0);
    FMA2(s1, a[3], b[3], s1);
    FMA2(s0, a[4], b[4], s0);
    FMA2(s1, a[5], b[5], s1);
    FMA2(s0, a[6], b[6], s0);
    FMA2(s1, a[7], b[7], s1);
    float l0, h0, l1, h1;
    UNPACK2(l0, h0, s0);
    UNPACK2(l1, h1, s1);
    return (l0 + h0) + (l1 + h1);
}

__device__ __forceinline__ void load16(uint64_t (&q)[8], uint32_t addr) {
    lds2(q[0], q[1], addr);
    lds2(q[2], q[3], addr + 16);
    lds2(q[4], q[5], addr + 32);
    lds2(q[6], q[7], addr + 48);
}
__device__ __forceinline__ void store_col(uint32_t addr, const uint64_t (&c)[8], float inv) {
    sts2(addr,      c[0], c[1]);
    sts2(addr + 16, c[2], c[3]);
    sts2(addr + 32, c[4], c[5]);
    sts2(addr + 48, c[6], c[7]);
    stsf(addr + 64, inv);
}

// MGS over 16 distributed columns. On exit: c = unnormalized orthogonal
// column j, nrm = ||c||^2.
__device__ __forceinline__ void mgs16(uint64_t (&c)[8], float& nrm, uint32_t base, int j) {
    nrm = dot16(c, c);
    if (j == 0) store_col(base, c, __fdividef(1.0f, fmaxf(nrm, 1e-35f)));
    uint64_t q[8];
    #pragma unroll
    for (int i = 0; i < 8; i++) q[i] = c[i];   // safe init (finite) for retired lanes
    float invqn = 0.0f;
    #pragma unroll 1
    for (int k = 0; k < 15; k++) {
        __syncwarp();
        const uint32_t ca = base + (uint32_t)k * 80u;
        const bool act = (j > k);
        if (act) {                        // predicated: no wavefronts when retired
            load16(q, ca);
            invqn = ldsf(ca + 64);
        }
        const float d = dot16(q, c);
        const float scale = act ? d * invqn : 0.0f;
        uint64_t ns2;
        const float ns = -scale;
        PACK2(ns2, ns, ns);
        #pragma unroll
        for (int i = 0; i < 8; i++) FMA2(c[i], ns2, q[i], c[i]);
        nrm = dot16(c, c);  // fresh norm (stability); stale lanes recompute same value
        if (j == k + 1)
            store_col(base + (uint32_t)j * 80u, c, __fdividef(1.0f, fmaxf(nrm, 1e-35f)));
    }
}

__global__ void __launch_bounds__(256)
inv1x1mm_svd_kernel(const float* __restrict__ data,
                    const float* __restrict__ paras,
                    float* __restrict__ out) {
    __shared__ __align__(16) float sm[POS_PER_BLOCK * BUFF];

    const int tid = threadIdx.x;
    const int pb  = tid >> 4;          // position within block (0..15)
    const int j   = tid & 15;          // column index
    const int pos = blockIdx.x * POS_PER_BLOCK + pb;

    const float* p = paras + (size_t)pos * PSTRIDE;
    const uint32_t base = smem_u32(&sm[pb * BUFF]);

    const float dval = __ldg(&data[pos * 16 + j]);
    const float ls   = __ldg(&p[j]);
    stsf(base + 1280u + (uint32_t)j * 4u, dval);  // data vector slot

    // ---- QR of U: lane j loads column j, packed in row pairs ----
    uint64_t c[8];
    #pragma unroll
    for (int i = 0; i < 8; i++) {
        const float lo = __ldg(&p[16 + (2 * i) * 16 + j]);
        const float hi = __ldg(&p[16 + (2 * i + 1) * 16 + j]);
        PACK2(c[i], lo, hi);
    }
    float nrm0;
    mgs16(c, nrm0, base, j);

    // v_j = (data . q0_j) / ||q0_j||;  w_j = v_j * exp(ls_j)
    uint64_t dv[8];
    load16(dv, base + 1280u);
    const float v = dot16(dv, c) * rsqrtf(fmaxf(nrm0, 1e-35f));
    const float w = v * __expf(ls);

    // ---- QR of V ----
    #pragma unroll
    for (int i = 0; i < 8; i++) {
        const float lo = __ldg(&p[272 + (2 * i) * 16 + j]);
        const float hi = __ldg(&p[272 + (2 * i + 1) * 16 + j]);
        PACK2(c[i], lo, hi);
    }
    float nrm1;
    mgs16(c, nrm1, base, j);

    // res_d = sum_j w'_j * q1col_j[d]  with w'_j = w_j / ||q1_j||
    const float wj = w * rsqrtf(fmaxf(nrm1, 1e-35f));
    uint64_t w2;
    PACK2(w2, wj, wj);
    #pragma unroll
    for (int i = 0; i < 8; i++) MUL2(c[i], w2, c[i]);

    __syncwarp();  // all reads of the QR2 column cache are done
    const uint32_t myslot = base + (uint32_t)j * 80u;
    sts2(myslot,      c[0], c[1]);
    sts2(myslot + 16, c[2], c[3]);
    sts2(myslot + 32, c[4], c[5]);
    sts2(myslot + 48, c[6], c[7]);
    __syncwarp();

    // lane j accumulates output element d=j: row j across the 16 stored columns
    float acc = 0.0f;
    #pragma unroll
    for (int jj = 0; jj < 16; jj++)
        acc += ldsf(base + (uint32_t)jj * 80u + (uint32_t)j * 4u);

    out[pos * 16 + j] = acc;
}

extern "C" void kernel_launch(void* const* d_in, const int* in_sizes, int n_in,
                              void* d_out, int out_size) {
    const float* data  = (const float*)d_in[0];
    const float* paras = (const float*)d_in[1];
    if (n_in >= 2 && in_sizes[0] > in_sizes[1]) {  // defensive ordering by size
        data  = (const float*)d_in[1];
        paras = (const float*)d_in[0];
    }
    inv1x1mm_svd_kernel<<<NPOS / POS_PER_BLOCK, 256>>>(data, paras, (float*)d_out);
}

// round 5
// speedup vs baseline: 1.0045x; 1.0045x over previous
#include <cuda_runtime.h>
#include <cstdint>

// Inv1x1MM_SVD, C=16, 65536 positions. 16 lanes per position, lane j owns
// column j of BOTH U and V in packed f32x2 registers. The two MGS sweeps are
// fused into one loop (independent dep chains -> 2x ILP). Finished column k
// is published to a shared-memory cache with its 1/||c||^2. Fresh norms each
// step (incremental tracking is unstable on ill-conditioned inputs).

constexpr int NPOS = 8 * 8192;
constexpr int PSTRIDE = 528;
constexpr int POS_PER_BLOCK = 8;        // 128 threads
constexpr int BUFF_B = 2624;            // bytes/position: U cache 1280 | V cache 1280 | data 64

#define FMA2(d, a, b, c) asm("fma.rn.f32x2 %0, %1, %2, %3;" : "=l"(d) : "l"(a), "l"(b), "l"(c))
#define MUL2(d, a, b)    asm("mul.rn.f32x2 %0, %1, %2;"     : "=l"(d) : "l"(a), "l"(b))
#define PACK2(d, lo, hi) asm("mov.b64 %0, {%1, %2};"        : "=l"(d) : "f"(lo), "f"(hi))
#define UNPACK2(lo, hi, d) asm("mov.b64 {%0, %1}, %2;" : "=f"(lo), "=f"(hi) : "l"(d))

__device__ __forceinline__ uint32_t smem_u32(const void* p) {
    uint32_t a;
    asm("{ .reg .u64 t; cvta.to.shared.u64 t, %1; cvt.u32.u64 %0, t; }" : "=r"(a) : "l"(p));
    return a;
}
__device__ __forceinline__ void lds2(uint64_t& a, uint64_t& b, uint32_t addr) {
    asm volatile("ld.shared.v2.u64 {%0, %1}, [%2];" : "=l"(a), "=l"(b) : "r"(addr));
}
__device__ __forceinline__ void sts2(uint32_t addr, uint64_t a, uint64_t b) {
    asm volatile("st.shared.v2.u64 [%0], {%1, %2};" :: "r"(addr), "l"(a), "l"(b) : "memory");
}
__device__ __forceinline__ float ldsf(uint32_t addr) {
    float v;
    asm volatile("ld.shared.f32 %0, [%1];" : "=f"(v) : "r"(addr));
    return v;
}
__device__ __forceinline__ void stsf(uint32_t addr, float v) {
    asm volatile("st.shared.f32 [%0], %1;" :: "r"(addr), "f"(v) : "memory");
}

// dot of two packed 16-vectors -> scalar, two accumulator trees
__device__ __forceinline__ float dot16(const uint64_t (&a)[8], const uint64_t (&b)[8]) {
    uint64_t s0, s1;
    MUL2(s0, a[0], b[0]);
    MUL2(s1, a[1], b[1]);
    FMA2(s0, a[2], b[2], s0);
    FMA2(s1, a[3], b[3], s1);
    FMA2(s0, a[4], b[4], s0);
    FMA2(s1, a[5], b[5], s1);
    FMA2(s0, a[6], b[6], s0);
    FMA2(s1, a[7], b[7], s1);
    float l0, h0, l1, h1;
    UNPACK2(l0, h0, s0);
    UNPACK2(l1, h1, s1);
    return (l0 + h0) + (l1 + h1);
}

__device__ __forceinline__ void load16(uint64_t (&q)[8], uint32_t addr) {
    lds2(q[0], q[1], addr);
    lds2(q[2], q[3], addr + 16);
    lds2(q[4], q[5], addr + 32);
    lds2(q[6], q[7], addr + 48);
}
__device__ __forceinline__ void store_col(uint32_t addr, const uint64_t (&c)[8], float inv) {
    sts2(addr,      c[0], c[1]);
    sts2(addr + 16, c[2], c[3]);
    sts2(addr + 32, c[4], c[5]);
    sts2(addr + 48, c[6], c[7]);
    stsf(addr + 64, inv);
}

__global__ void __launch_bounds__(128)
inv1x1mm_svd_kernel(const float* __restrict__ data,
                    const float* __restrict__ paras,
                    float* __restrict__ out) {
    __shared__ __align__(16) char smraw[POS_PER_BLOCK * BUFF_B];

    const int tid = threadIdx.x;
    const int pb  = tid >> 4;           // position within block (0..7)
    const int j   = tid & 15;           // column index
    const int pos = blockIdx.x * POS_PER_BLOCK + pb;

    const float* p = paras + (size_t)pos * PSTRIDE;
    const uint32_t base  = smem_u32(smraw) + (uint32_t)pb * BUFF_B;
    const uint32_t vbase = base + 1280u;

    const float dval = __ldg(&data[pos * 16 + j]);
    const float ls   = __ldg(&p[j]);
    stsf(base + 2560u + (uint32_t)j * 4u, dval);   // data vector slot

    // ---- lane j loads column j of U and of V, packed in row pairs ----
    uint64_t cu[8], cv[8];
    #pragma unroll
    for (int i = 0; i < 8; i++) {
        float lo = __ldg(&p[16 + (2 * i) * 16 + j]);
        float hi = __ldg(&p[16 + (2 * i + 1) * 16 + j]);
        PACK2(cu[i], lo, hi);
        lo = __ldg(&p[272 + (2 * i) * 16 + j]);
        hi = __ldg(&p[272 + (2 * i + 1) * 16 + j]);
        PACK2(cv[i], lo, hi);
    }

    float nu = dot16(cu, cu);
    float nv = dot16(cv, cv);
    if (j == 0) {
        store_col(base,  cu, __fdividef(1.0f, fmaxf(nu, 1e-35f)));
        store_col(vbase, cv, __fdividef(1.0f, fmaxf(nv, 1e-35f)));
    }

    uint64_t qu[8], qv[8];
    #pragma unroll
    for (int i = 0; i < 8; i++) { qu[i] = cu[i]; qv[i] = cv[i]; }  // safe init
    float iqu = 0.0f, iqv = 0.0f;

    // ---- fused MGS sweep over both matrices ----
    #pragma unroll 1
    for (int k = 0; k < 15; k++) {
        __syncwarp();
        const uint32_t off = (uint32_t)k * 80u;
        const bool act = (j > k);
        if (act) {
            load16(qu, base + off);
            iqu = ldsf(base + off + 64);
            load16(qv, vbase + off);
            iqv = ldsf(vbase + off + 64);
        }
        const float du = dot16(qu, cu);
        const float dv = dot16(qv, cv);
        const float su = act ? du * iqu : 0.0f;
        const float sv = act ? dv * iqv : 0.0f;
        uint64_t nsu, nsv;
        const float msu = -su, msv = -sv;
        PACK2(nsu, msu, msu);
        PACK2(nsv, msv, msv);
        #pragma unroll
        for (int i = 0; i < 8; i++) {
            FMA2(cu[i], nsu, qu[i], cu[i]);
            FMA2(cv[i], nsv, qv[i], cv[i]);
        }
        nu = dot16(cu, cu);   // fresh norms (stability)
        nv = dot16(cv, cv);
        if (j == k + 1) {
            const uint32_t moff = (uint32_t)j * 80u;
            store_col(base + moff,  cu, __fdividef(1.0f, fmaxf(nu, 1e-35f)));
            store_col(vbase + moff, cv, __fdividef(1.0f, fmaxf(nv, 1e-35f)));
        }
    }

    // v_j = (data . q0_j)/||q0_j||;  w_j = v_j * exp(ls_j);  w'_j = w_j/||q1_j||
    uint64_t dv8[8];
    load16(dv8, base + 2560u);
    const float v  = dot16(dv8, cu) * rsqrtf(fmaxf(nu, 1e-35f));
    const float wj = v * __expf(ls) * rsqrtf(fmaxf(nv, 1e-35f));
    uint64_t w2;
    PACK2(w2, wj, wj);
    #pragma unroll
    for (int i = 0; i < 8; i++) MUL2(cv[i], w2, cv[i]);

    __syncwarp();   // all reads of the V column cache are done
    const uint32_t myslot = vbase + (uint32_t)j * 80u;
    sts2(myslot,      cv[0], cv[1]);
    sts2(myslot + 16, cv[2], cv[3]);
    sts2(myslot + 32, cv[4], cv[5]);
    sts2(myslot + 48, cv[6], cv[7]);
    __syncwarp();

    // res_d (d = j): row j across the 16 scaled V columns
    float acc = 0.0f;
    #pragma unroll
    for (int jj = 0; jj < 16; jj++)
        acc += ldsf(vbase + (uint32_t)jj * 80u + (uint32_t)j * 4u);

    out[pos * 16 + j] = acc;
}

extern "C" void kernel_launch(void* const* d_in, const int* in_sizes, int n_in,
                              void* d_out, int out_size) {
    const float* data  = (const float*)d_in[0];
    const float* paras = (const float*)d_in[1];
    if (n_in >= 2 && in_sizes[0] > in_sizes[1]) {  // defensive ordering by size
        data  = (const float*)d_in[1];
        paras = (const float*)d_in[0];
    }
    inv1x1mm_svd_kernel<<<NPOS / POS_PER_BLOCK, 128>>>(data, paras, (float*)d_out);
}

// round 6
// speedup vs baseline: 1.8388x; 1.8305x over previous
#include <cuda_runtime.h>
#include <cstdint>

// Inv1x1MM_SVD, C=16, 65536 positions.
// ROW-SLAB layout: 2 lanes per position; lane (pos, half) holds rows
// half*8..half*8+7 of the working 16x16 matrix, all 16 columns, packed as
// f32x2 column pairs in registers (A[i][c] = cols {2c,2c+1} of local row i).
// MGS step k: column k is lane-local; dots for all j>=k computed locally and
// reduced across the lane pair (1 shfl-xor). Norm p[k] comes free and fresh.
// Updates are lane-local rank-1 FMA2s. Near-zero MIO per step.

constexpr int NPOS = 8 * 8192;

#define FMA2(d, a, b, c) asm("fma.rn.f32x2 %0, %1, %2, %3;" : "=l"(d) : "l"(a), "l"(b), "l"(c))
#define MUL2(d, a, b)    asm("mul.rn.f32x2 %0, %1, %2;"     : "=l"(d) : "l"(a), "l"(b))
#define ADD2(d, a, b)    asm("add.rn.f32x2 %0, %1, %2;"     : "=l"(d) : "l"(a), "l"(b))
#define PACK2(d, lo, hi) asm("mov.b64 %0, {%1, %2};"        : "=l"(d) : "f"(lo), "f"(hi))
#define UNPACK2(lo, hi, d) asm("mov.b64 {%0, %1}, %2;" : "=f"(lo), "=f"(hi) : "l"(d))

// 64-bit shfl-xor with the partner lane (xor 1)
__device__ __forceinline__ uint64_t shx1(uint64_t v) {
    uint32_t lo, hi;
    asm("mov.b64 {%0, %1}, %2;" : "=r"(lo), "=r"(hi) : "l"(v));
    lo = __shfl_xor_sync(0xffffffffu, lo, 1);
    hi = __shfl_xor_sync(0xffffffffu, hi, 1);
    uint64_t r;
    asm("mov.b64 %0, {%1, %2};" : "=l"(r) : "r"(lo), "r"(hi));
    return r;
}

// MGS over 16 columns held as row-slabs across a lane pair.
// On exit: A holds orthogonal (unnormalized) columns b_j; rs[j] = 1/||b_j||.
__device__ __forceinline__ void mgs(uint64_t (&A)[8][8], float (&rs)[16]) {
    #pragma unroll
    for (int k = 0; k < 15; k++) {
        const int c0 = k >> 1;        // first pair containing j >= k
        const int cu = (k + 1) >> 1;  // first pair updated

        // broadcast-free: column k elements are local (row i, col k)
        uint64_t ak[8];
        #pragma unroll
        for (int i = 0; i < 8; i++) {
            float lo, hi;
            UNPACK2(lo, hi, A[i][c0]);
            const float x = (k & 1) ? hi : lo;
            PACK2(ak[i], x, x);
        }

        // dots p_j = <c_k, c_j> for all j >= k (pairwise), reduced over lane pair
        uint64_t pp[8];
        #pragma unroll
        for (int c = 0; c < 8; c++) {
            if (c < c0) continue;
            MUL2(pp[c], ak[0], A[0][c]);
            #pragma unroll
            for (int i = 1; i < 8; i++) FMA2(pp[c], ak[i], A[i][c], pp[c]);
            const uint64_t o = shx1(pp[c]);
            ADD2(pp[c], pp[c], o);
        }

        // fresh norm ||c_k||^2 = p_k (same pass)
        float plo, phi;
        UNPACK2(plo, phi, pp[c0]);
        const float pk = (k & 1) ? phi : plo;
        const float r  = rsqrtf(fmaxf(pk, 1e-30f));
        rs[k] = r;
        const float ninv = -(r * r);   // -1/||c_k||^2
        uint64_t n2;
        PACK2(n2, ninv, ninv);

        // updates c_j -= (p_j/||c_k||^2) c_k for j > k
        #pragma unroll
        for (int c = 0; c < 8; c++) {
            if (c < cu) continue;
            uint64_t s;
            MUL2(s, pp[c], n2);
            if (!(k & 1) && c == cu) {     // pair contains j == k: zero its lo scale
                float slo, shi;
                UNPACK2(slo, shi, s);
                PACK2(s, 0.0f, shi);
            }
            #pragma unroll
            for (int i = 0; i < 8; i++) FMA2(A[i][c], s, ak[i], A[i][c]);
        }
    }
    // norm of column 15
    float n15 = 0.0f;
    #pragma unroll
    for (int i = 0; i < 8; i++) {
        float lo, hi;
        UNPACK2(lo, hi, A[i][7]);
        n15 = fmaf(hi, hi, n15);
    }
    n15 += __shfl_xor_sync(0xffffffffu, n15, 1);
    rs[15] = rsqrtf(fmaxf(n15, 1e-30f));
}

__device__ __forceinline__ void load_mat(uint64_t (&A)[8][8], const float4* f4, int rbase) {
    #pragma unroll
    for (int i = 0; i < 8; i++) {
        const float4 q0 = __ldg(&f4[rbase + 4 * i + 0]);
        const float4 q1 = __ldg(&f4[rbase + 4 * i + 1]);
        const float4 q2 = __ldg(&f4[rbase + 4 * i + 2]);
        const float4 q3 = __ldg(&f4[rbase + 4 * i + 3]);
        PACK2(A[i][0], q0.x, q0.y); PACK2(A[i][1], q0.z, q0.w);
        PACK2(A[i][2], q1.x, q1.y); PACK2(A[i][3], q1.z, q1.w);
        PACK2(A[i][4], q2.x, q2.y); PACK2(A[i][5], q2.z, q2.w);
        PACK2(A[i][6], q3.x, q3.y); PACK2(A[i][7], q3.z, q3.w);
    }
}

__global__ void __launch_bounds__(64)
inv1x1mm_svd_kernel(const float* __restrict__ data,
                    const float* __restrict__ paras,
                    float* __restrict__ out) {
    const int tid  = threadIdx.x;
    const int half = tid & 1;                      // which 8-row slab
    const int pos  = blockIdx.x * 32 + (tid >> 1); // 32 positions per block

    const float4* f4 = (const float4*)(paras + (size_t)pos * 528);
    const int rbase_u = 4 + half * 32;             // float4 index of my first U row
    const int rbase_v = 68 + half * 32;            // my first V row

    uint64_t A[8][8];
    float rs0[16], rs1[16];

    // ===== QR of U =====
    load_mat(A, f4, rbase_u);
    mgs(A, rs0);

    // v_j = <data, b0_j> (reduced over pair); both lanes end with all 16
    const float4 d0 = __ldg((const float4*)(data + pos * 16 + half * 8));
    const float4 d1 = __ldg((const float4*)(data + pos * 16 + half * 8 + 4));
    uint64_t dd[8];
    PACK2(dd[0], d0.x, d0.x); PACK2(dd[1], d0.y, d0.y);
    PACK2(dd[2], d0.z, d0.z); PACK2(dd[3], d0.w, d0.w);
    PACK2(dd[4], d1.x, d1.x); PACK2(dd[5], d1.y, d1.y);
    PACK2(dd[6], d1.z, d1.z); PACK2(dd[7], d1.w, d1.w);

    uint64_t w[8];
    #pragma unroll
    for (int c = 0; c < 8; c++) {
        MUL2(w[c], dd[0], A[0][c]);
        #pragma unroll
        for (int i = 1; i < 8; i++) FMA2(w[c], dd[i], A[i][c], w[c]);
        const uint64_t o = shx1(w[c]);
        ADD2(w[c], w[c], o);
    }

    // w_j = v_j * rs0_j * exp(ls_j)   (both lanes compute all 16)
    const float4 l0 = __ldg(&f4[0]);
    const float4 l1 = __ldg(&f4[1]);
    const float4 l2 = __ldg(&f4[2]);
    const float4 l3 = __ldg(&f4[3]);
    const float e[16] = {
        __expf(l0.x), __expf(l0.y), __expf(l0.z), __expf(l0.w),
        __expf(l1.x), __expf(l1.y), __expf(l1.z), __expf(l1.w),
        __expf(l2.x), __expf(l2.y), __expf(l2.z), __expf(l2.w),
        __expf(l3.x), __expf(l3.y), __expf(l3.z), __expf(l3.w)};
    #pragma unroll
    for (int c = 0; c < 8; c++) {
        uint64_t m;
        PACK2(m, e[2 * c] * rs0[2 * c], e[2 * c + 1] * rs0[2 * c + 1]);
        MUL2(w[c], w[c], m);
    }

    // ===== QR of V =====
    load_mat(A, f4, rbase_v);
    mgs(A, rs1);

    // w'_j = w_j * rs1_j ; res_d = sum_j w'_j * b1[d][j]  (lane-local rows)
    #pragma unroll
    for (int c = 0; c < 8; c++) {
        uint64_t m;
        PACK2(m, rs1[2 * c], rs1[2 * c + 1]);
        MUL2(w[c], w[c], m);
    }

    float o[8];
    #pragma unroll
    for (int i = 0; i < 8; i++) {
        uint64_t acc;
        MUL2(acc, w[0], A[i][0]);
        #pragma unroll
        for (int c = 1; c < 8; c++) FMA2(acc, w[c], A[i][c], acc);
        float lo, hi;
        UNPACK2(lo, hi, acc);
        o[i] = lo + hi;
    }

    float4* o4 = (float4*)(out + pos * 16 + half * 8);
    o4[0] = make_float4(o[0], o[1], o[2], o[3]);
    o4[1] = make_float4(o[4], o[5], o[6], o[7]);
}

extern "C" void kernel_launch(void* const* d_in, const int* in_sizes, int n_in,
                              void* d_out, int out_size) {
    const float* data  = (const float*)d_in[0];
    const float* paras = (const float*)d_in[1];
    if (n_in >= 2 && in_sizes[0] > in_sizes[1]) {  // defensive ordering by size
        data  = (const float*)d_in[1];
        paras = (const float*)d_in[0];
    }
    inv1x1mm_svd_kernel<<<NPOS / 32, 64>>>(data, paras, (float*)d_out);
}